// round 12
// baseline (speedup 1.0000x reference)
#include <cuda_runtime.h>

// Problem dims (fixed by the reference)
#define Bn  4
#define Qn  256
#define KVn 1024
#define Hn  128
#define VSn 256

#define CHK 512                 // KV chunk size (2 chunks)

// Scratch (no cudaMalloc allowed)
__device__ float g_Eq[Bn * Qn * Hn];    // e^{2*clamp(q_proj)}
__device__ float g_Ek[Bn * KVn * Hn];   // e^{2*clamp(k_proj)}
__device__ float g_pS[2][Bn * Qn][VSn]; // per-chunk unnormalized AV partials
__device__ float g_pM[2][Bn * Qn];      // per-chunk score max
__device__ float g_pZ[2][Bn * Qn];      // per-chunk exp-sum

// 2*log2(e): e^{2x} = 2^{x * 2*log2(e)}
#define TWO_LOG2E 2.885390081777927f

// ---------------------------------------------------------------------------
// Kernel 1: project rows, emit E = exp2(clamp(proj, +-40) * 2*log2(e)).
// Key rows >= valid_len are skipped entirely (never read downstream).
// ---------------------------------------------------------------------------
__global__ __launch_bounds__(256)
void proj_kernel(const float* __restrict__ queries,
                 const float* __restrict__ keys,
                 const float* __restrict__ Wq,
                 const float* __restrict__ Wk,
                 const int* __restrict__ valid_lens) {
    const int r0 = blockIdx.x * 8;
    const float* in;
    const float* W;
    float* outp;
    if (r0 < Bn * Qn) {
        in   = queries + r0 * Hn;
        W    = Wq;
        outp = g_Eq + r0 * Hn;
    } else {
        const int rr = r0 - Bn * Qn;          // global key row
        const int b  = rr >> 10;              // / KVn
        const int j0 = rr & (KVn - 1);
        if (j0 >= valid_lens[b]) return;      // these Ek rows are never read
        in   = keys + rr * Hn;
        W    = Wk;
        outp = g_Ek + rr * Hn;
    }
    __shared__ float s[8][Hn];
    const int t = threadIdx.x;
    #pragma unroll
    for (int u = 0; u < 4; u++) {
        const int idx = t + u * 256;
        s[idx >> 7][idx & 127] = in[idx];
    }
    __syncthreads();

    const int rg  = t >> 7;
    const int col = t & 127;

    float a[4];
    #pragma unroll
    for (int r = 0; r < 4; r++) a[r] = 0.f;

    #pragma unroll 8
    for (int kk = 0; kk < Hn; kk++) {
        const float w = W[kk * Hn + col];
        #pragma unroll
        for (int r = 0; r < 4; r++)
            a[r] = fmaf(s[rg * 4 + r][kk], w, a[r]);
    }
    #pragma unroll
    for (int r = 0; r < 4; r++) {
        float p = fminf(fmaxf(a[r], -40.f), 40.f) * TWO_LOG2E;
        float e;
        asm("ex2.approx.f32 %0, %1;" : "=f"(e) : "f"(p));
        outp[(rg * 4 + r) * Hn + col] = e;
    }
}

// ---------------------------------------------------------------------------
// Kernel 2: split-KV score + local softmax + partial AV.
// grid 1024: bid -> (pair = bid>>1, chunk = bid&1). 256 threads.
// Batch map b=(pair+(pair>>2))&3 keeps same-SM blocks cycling batches.
// Emits, per (row, chunk): M (local max), Z (local exp-sum), and the
// UNNORMALIZED S[c] = sum_j e^{s_j - M} * v[j][c]. Empty chunks emit
// M=-3e38, Z=0, S=0. L==0 (all masked -> uniform) emits M=0, Z=CHK, S=sum(v).
// ---------------------------------------------------------------------------
__global__ __launch_bounds__(256, 4)
void score_chunk_kernel(const float* __restrict__ values,
                        const int* __restrict__ valid_lens,
                        const float* __restrict__ wv) {
    const int bid   = blockIdx.x;
    const int pair  = bid >> 1;
    const int chunk = bid & 1;
    const int qp    = pair >> 2;
    const int b     = (pair + qp) & 3;
    const int row0  = (b << 8) + (qp << 1);
    const int row1  = row0 + 1;
    const int tid   = threadIdx.x;
    const int lane  = tid & 31;
    const int warp  = tid >> 5;

    __shared__ float s_sc[2][CHK];
    __shared__ float s_av[2][4][VSn];
    __shared__ float s_rmax[2][8];
    __shared__ float s_rsum[2][8];

    const int L    = valid_lens[b];
    const bool uni = (L <= 0);
    const int c0   = chunk * CHK;

    // Empty chunk: L > 0 but this chunk entirely masked.
    if (!uni && c0 >= L) {
        g_pS[chunk][row0][tid] = 0.f;
        g_pS[chunk][row1][tid] = 0.f;
        if (tid == 0) {
            g_pM[chunk][row0] = -3.0e38f;  g_pZ[chunk][row0] = 0.f;
            g_pM[chunk][row1] = -3.0e38f;  g_pZ[chunk][row1] = 0.f;
        }
        return;
    }

    const int clen = uni ? CHK : ((c0 + CHK < L) ? CHK : (L - c0));

    float M0, M1, Z0, Z1;
    if (!uni) {
        // ---- scores for both query rows over keys [c0, c0+clen) ----
        const int sub = lane >> 4;          // which key of the duo (0..1)
        const int hb  = (lane & 15) << 3;   // h-chunk base (8 floats)

        float4 qa[2], qb[2], w2[2];
        float wsum_l = 0.f;
        #pragma unroll
        for (int i = 0; i < 2; i++) {
            qa[i] = *reinterpret_cast<const float4*>(&g_Eq[row0 * Hn + hb + i * 4]);
            qb[i] = *reinterpret_cast<const float4*>(&g_Eq[row1 * Hn + hb + i * 4]);
            float4 w = *reinterpret_cast<const float4*>(&wv[hb + i * 4]);
            wsum_l += ((w.x + w.y) + (w.z + w.w));
            w2[i] = make_float4(-2.f * w.x, -2.f * w.y, -2.f * w.z, -2.f * w.w);
        }
        const float* kbp = g_Ek + (b * KVn + c0) * Hn;

        for (int j0 = warp * 2; j0 < clen; j0 += 16) {
            const int key = j0 + sub;                         // chunk-local
            const int kc  = (key < clen) ? key : (clen - 1);  // safe load

            float4 k4[2];
            #pragma unroll
            for (int i = 0; i < 2; i++)
                k4[i] = *reinterpret_cast<const float4*>(&kbp[kc * Hn + hb + i * 4]);

            float sa0 = wsum_l, sb0 = 0.f, sa1 = wsum_l, sb1 = 0.f;
            #pragma unroll
            for (int i = 0; i < 2; i++) {
                // query row0: w0/d0 + w1/d1 = (w0*d1c + w1*d0c)*rcp(d0c*d1c)
                float d0 = fminf(fmaf(qa[i].x, k4[i].x, 1.f), 1e18f);
                float d1 = fminf(fmaf(qa[i].y, k4[i].y, 1.f), 1e18f);
                float d2 = fminf(fmaf(qa[i].z, k4[i].z, 1.f), 1e18f);
                float d3 = fminf(fmaf(qa[i].w, k4[i].w, 1.f), 1e18f);
                float n01 = fmaf(w2[i].x, d1, w2[i].y * d0);
                float n23 = fmaf(w2[i].z, d3, w2[i].w * d2);
                float r01, r23;
                asm("rcp.approx.f32 %0, %1;" : "=f"(r01) : "f"(d0 * d1));
                asm("rcp.approx.f32 %0, %1;" : "=f"(r23) : "f"(d2 * d3));
                sa0 = fmaf(n01, r01, sa0);
                sb0 = fmaf(n23, r23, sb0);
                // query row1
                float e0 = fminf(fmaf(qb[i].x, k4[i].x, 1.f), 1e18f);
                float e1 = fminf(fmaf(qb[i].y, k4[i].y, 1.f), 1e18f);
                float e2 = fminf(fmaf(qb[i].z, k4[i].z, 1.f), 1e18f);
                float e3 = fminf(fmaf(qb[i].w, k4[i].w, 1.f), 1e18f);
                float m01 = fmaf(w2[i].x, e1, w2[i].y * e0);
                float m23 = fmaf(w2[i].z, e3, w2[i].w * e2);
                float u01, u23;
                asm("rcp.approx.f32 %0, %1;" : "=f"(u01) : "f"(e0 * e1));
                asm("rcp.approx.f32 %0, %1;" : "=f"(u23) : "f"(e2 * e3));
                sa1 = fmaf(m01, u01, sa1);
                sb1 = fmaf(m23, u23, sb1);
            }
            float s = sa0 + sb0;
            float t = sa1 + sb1;

            s += __shfl_xor_sync(0xffffffffu, s, 1);
            t += __shfl_xor_sync(0xffffffffu, t, 1);
            s += __shfl_xor_sync(0xffffffffu, s, 2);
            t += __shfl_xor_sync(0xffffffffu, t, 2);
            s += __shfl_xor_sync(0xffffffffu, s, 4);
            t += __shfl_xor_sync(0xffffffffu, t, 4);
            s += __shfl_xor_sync(0xffffffffu, s, 8);
            t += __shfl_xor_sync(0xffffffffu, t, 8);

            if ((lane & 15) == 0 && key < clen) {
                s_sc[0][key] = s;
                s_sc[1][key] = t;
            }
        }
        __syncthreads();

        // ---- local max (race-free: separate scratch arrays) ----
        #pragma unroll
        for (int r = 0; r < 2; r++) {
            float m = -3.0e38f;
            for (int jj = tid; jj < clen; jj += 256) m = fmaxf(m, s_sc[r][jj]);
            #pragma unroll
            for (int o = 16; o > 0; o >>= 1)
                m = fmaxf(m, __shfl_xor_sync(0xffffffffu, m, o));
            if (lane == 0) s_rmax[r][warp] = m;
        }
        __syncthreads();

        // ---- exp + local sum ----
        #pragma unroll
        for (int r = 0; r < 2; r++) {
            float M = s_rmax[r][0];
            #pragma unroll
            for (int k = 1; k < 8; k++) M = fmaxf(M, s_rmax[r][k]);

            float z = 0.f;
            for (int jj = tid; jj < clen; jj += 256) {
                const float e = __expf(s_sc[r][jj] - M);
                s_sc[r][jj] = e;
                z += e;
            }
            #pragma unroll
            for (int o = 16; o > 0; o >>= 1)
                z += __shfl_xor_sync(0xffffffffu, z, o);
            if (lane == 0) s_rsum[r][warp] = z;
        }
        __syncthreads();
        M0 = s_rmax[0][0]; M1 = s_rmax[1][0];
        #pragma unroll
        for (int k = 1; k < 8; k++) {
            M0 = fmaxf(M0, s_rmax[0][k]);
            M1 = fmaxf(M1, s_rmax[1][k]);
        }
        Z0 = s_rsum[0][0]; Z1 = s_rsum[1][0];
        #pragma unroll
        for (int k = 1; k < 8; k++) {
            Z0 += s_rsum[0][k];
            Z1 += s_rsum[1][k];
        }
    } else {
        // L == 0: softmax over all -1e6 -> uniform. Chunk emits weight 1/key.
        for (int jj = tid; jj < CHK; jj += 256) {
            s_sc[0][jj] = 1.0f;
            s_sc[1][jj] = 1.0f;
        }
        __syncthreads();
        M0 = 0.f; M1 = 0.f;
        Z0 = (float)CHK; Z1 = (float)CHK;
    }

    // ---- partial AV (unnormalized), LDG.128 geometry ----
    const int c4   = (tid & 63) << 2;
    const int joff = tid >> 6;
    const float* vrow = values + (size_t)(b * KVn + c0) * VSn + c4;

    float a0x = 0.f, a0y = 0.f, a0z = 0.f, a0w = 0.f;
    float a1x = 0.f, a1y = 0.f, a1z = 0.f, a1w = 0.f;
    #pragma unroll 4
    for (int j = joff; j < clen; j += 4) {
        const float4 v = *reinterpret_cast<const float4*>(vrow + (size_t)j * VSn);
        const float p0 = s_sc[0][j];
        const float p1 = s_sc[1][j];
        a0x = fmaf(p0, v.x, a0x);  a1x = fmaf(p1, v.x, a1x);
        a0y = fmaf(p0, v.y, a0y);  a1y = fmaf(p1, v.y, a1y);
        a0z = fmaf(p0, v.z, a0z);  a1z = fmaf(p1, v.z, a1z);
        a0w = fmaf(p0, v.w, a0w);  a1w = fmaf(p1, v.w, a1w);
    }
    *reinterpret_cast<float4*>(&s_av[0][joff][c4]) = make_float4(a0x, a0y, a0z, a0w);
    *reinterpret_cast<float4*>(&s_av[1][joff][c4]) = make_float4(a1x, a1y, a1z, a1w);
    __syncthreads();

    {
        const int c = tid;
        g_pS[chunk][row0][c] = (s_av[0][0][c] + s_av[0][1][c]) +
                               (s_av[0][2][c] + s_av[0][3][c]);
        g_pS[chunk][row1][c] = (s_av[1][0][c] + s_av[1][1][c]) +
                               (s_av[1][2][c] + s_av[1][3][c]);
    }
    if (tid == 0) {
        g_pM[chunk][row0] = M0;  g_pZ[chunk][row0] = Z0;
        g_pM[chunk][row1] = M1;  g_pZ[chunk][row1] = Z1;
    }
}

// ---------------------------------------------------------------------------
// Kernel 3: combine the two chunk partials per row.
// out = (w0*S0 + w1*S1) / (w0*Z0 + w1*Z1), w_c = e^{M_c - max(M0,M1)}.
// Empty chunk (M=-3e38) -> w=0. Chunk 0 is nonempty whenever L>0, and both
// chunks are populated when L==0 (uniform), so the denominator is > 0.
// ---------------------------------------------------------------------------
__global__ __launch_bounds__(256)
void combine_kernel(float* __restrict__ out) {
    const int row0 = blockIdx.x * 2;
    const int tid  = threadIdx.x;

    #pragma unroll
    for (int r = 0; r < 2; r++) {
        const int row = row0 + r;
        const float M0 = g_pM[0][row], M1 = g_pM[1][row];
        const float Z0 = g_pZ[0][row], Z1 = g_pZ[1][row];
        const float M  = fmaxf(M0, M1);
        const float w0 = __expf(M0 - M);
        const float w1 = __expf(M1 - M);
        const float denom = fmaf(w0, Z0, w1 * Z1);
        const float inv = 1.0f / denom;
        const float s = fmaf(w0, g_pS[0][row][tid], w1 * g_pS[1][row][tid]);
        out[row * VSn + tid] = s * inv;
    }
}

// ---------------------------------------------------------------------------
extern "C" void kernel_launch(void* const* d_in, const int* in_sizes, int n_in,
                              void* d_out, int out_size) {
    const float* queries = (const float*)d_in[0];
    const float* keys    = (const float*)d_in[1];
    const float* values  = (const float*)d_in[2];
    const int*   valid   = (const int*)d_in[3];
    const float* Wq      = (const float*)d_in[4];
    const float* Wk      = (const float*)d_in[5];
    const float* wv      = (const float*)d_in[6];
    float* out           = (float*)d_out;

    proj_kernel<<<(Bn * Qn + Bn * KVn) / 8, 256>>>(queries, keys, Wq, Wk, valid);
    score_chunk_kernel<<<Bn * Qn, 256>>>(values, valid, wv);   // 1024 blocks
    combine_kernel<<<(Bn * Qn) / 2, 256>>>(out);
}